// round 13
// baseline (speedup 1.0000x reference)
#include <cuda_runtime.h>

#define D     64
#define PD    68            // padded smem row stride: 16B-aligned rows, conflict-free LDS.128
#define NMAX  12288
#define FULL  0xffffffffu
#define CAPG  128           // per-row nonzero list capacity (mean ~25, 20+ sigma headroom)
#define HQKB  148           // blocks doing hqk (one per SM in wave 1)

// Scratch (allocation-free contract: __device__ globals)
__device__ float g_h [NMAX * D];
__device__ float g_qm[NMAX * D];            // q with first component pre-negated
__device__ float g_k [NMAX * D];
__device__ int   g_cnt [NMAX];
__device__ int2  g_list[(size_t)NMAX * CAPG];   // {col j, float bits of adj value}

// 4-rows-per-warp cooperative 64x64 matvec; weights as float4 from padded smem.
__device__ __forceinline__ void matvec4(const float* __restrict__ sW,
                                        const float v0[4], const float v1[4],
                                        float bb0, float bb1, int lane,
                                        float o0[4], float o1[4])
{
    const float4* r0 = (const float4*)(sW + lane * PD);
    const float4* r1 = (const float4*)(sW + (lane + 32) * PD);
    float a0[4], a1[4];
#pragma unroll
    for (int k = 0; k < 4; k++) { a0[k] = bb0; a1[k] = bb1; }
#pragma unroll
    for (int c4 = 0; c4 < 8; c4++) {
        float4 w0 = r0[c4], w1 = r1[c4];
#pragma unroll
        for (int k = 0; k < 4; k++) {
            float x0 = __shfl_sync(FULL, v0[k], 4 * c4 + 0);
            float x1 = __shfl_sync(FULL, v0[k], 4 * c4 + 1);
            float x2 = __shfl_sync(FULL, v0[k], 4 * c4 + 2);
            float x3 = __shfl_sync(FULL, v0[k], 4 * c4 + 3);
            a0[k] = fmaf(x0, w0.x, a0[k]); a1[k] = fmaf(x0, w1.x, a1[k]);
            a0[k] = fmaf(x1, w0.y, a0[k]); a1[k] = fmaf(x1, w1.y, a1[k]);
            a0[k] = fmaf(x2, w0.z, a0[k]); a1[k] = fmaf(x2, w1.z, a1[k]);
            a0[k] = fmaf(x3, w0.w, a0[k]); a1[k] = fmaf(x3, w1.w, a1[k]);
        }
    }
#pragma unroll
    for (int c4 = 8; c4 < 16; c4++) {
        float4 w0 = r0[c4], w1 = r1[c4];
#pragma unroll
        for (int k = 0; k < 4; k++) {
            float x0 = __shfl_sync(FULL, v1[k], 4 * (c4 - 8) + 0);
            float x1 = __shfl_sync(FULL, v1[k], 4 * (c4 - 8) + 1);
            float x2 = __shfl_sync(FULL, v1[k], 4 * (c4 - 8) + 2);
            float x3 = __shfl_sync(FULL, v1[k], 4 * (c4 - 8) + 3);
            a0[k] = fmaf(x0, w0.x, a0[k]); a1[k] = fmaf(x0, w1.x, a1[k]);
            a0[k] = fmaf(x1, w0.y, a0[k]); a1[k] = fmaf(x1, w1.y, a1[k]);
            a0[k] = fmaf(x2, w0.z, a0[k]); a1[k] = fmaf(x2, w1.z, a1[k]);
            a0[k] = fmaf(x3, w0.w, a0[k]); a1[k] = fmaf(x3, w1.w, a1[k]);
        }
    }
#pragma unroll
    for (int k = 0; k < 4; k++) { o0[k] = a0[k]; o1[k] = a1[k]; }
}

__device__ __forceinline__ void lorentzify(float& h0, float& h1, float escale, int lane)
{
    float t    = __shfl_sync(FULL, h0, 0);
    float time = escale / (1.0f + __expf(-t)) + 1.1f;
    float sq   = ((lane == 0) ? 0.0f : h0 * h0) + h1 * h1;
#pragma unroll
    for (int o = 16; o > 0; o >>= 1) sq += __shfl_xor_sync(FULL, sq, o);
    sq = fmaxf(sq, 1e-8f);
    float ss = sqrtf((time * time - 1.0f) / sq);
    h0 = (lane == 0) ? time : h0 * ss;
    h1 *= ss;
}

// Blocks [0,HQKB): compute h/qm/k (hidden under the adj stream).
// Blocks [HQKB,..): one warp per adj row — stream adj, append nonzeros to
// per-row global lists.
__global__ void __launch_bounds__(256)
fused1_kernel(const float* __restrict__ x,
              const float* __restrict__ W,  const float* __restrict__ b,  const float* __restrict__ scale,
              const float* __restrict__ Wq, const float* __restrict__ bq, const float* __restrict__ scale_q,
              const float* __restrict__ Wk, const float* __restrict__ bk, const float* __restrict__ scale_k,
              const float* __restrict__ adj, int N)
{
    __shared__ __align__(16) float sA[D * PD];
    __shared__ __align__(16) float sB[D * PD];

    const int lane = threadIdx.x & 31;

    if (blockIdx.x >= HQKB) {
        // ---------------- scan role: one warp per adj row ----------------
        const int i = (blockIdx.x - HQKB) * 8 + (threadIdx.x >> 5);
        if (i >= N) return;
        if (lane == 0) g_cnt[i] = 0;
        __syncwarp();

        const float4* arow = (const float4*)(adj + (size_t)i * N);
        const int nf4 = N >> 2;
        int2* lst = g_list + (size_t)i * CAPG;

        for (int it = 0; it < nf4; it += 256) {          // 1024 cols/iter, MLP=8
            float4 a[8];
#pragma unroll
            for (int u = 0; u < 8; u++) {
                int idx = it + u * 32 + lane;
                a[u] = (idx < nf4) ? __ldcs(&arow[idx]) : make_float4(0.f, 0.f, 0.f, 0.f);
            }
#pragma unroll
            for (int u = 0; u < 8; u++) {
                float4 v = a[u];
                if ((v.x != 0.0f) | (v.y != 0.0f) | (v.z != 0.0f) | (v.w != 0.0f)) {
                    int base = (it + u * 32 + lane) * 4;
                    int n = (v.x != 0.0f) + (v.y != 0.0f) + (v.z != 0.0f) + (v.w != 0.0f);
                    int slot = atomicAdd(&g_cnt[i], n);
                    if (v.x != 0.0f && slot < CAPG) { lst[slot] = make_int2(base,     __float_as_int(v.x)); slot++; }
                    if (v.y != 0.0f && slot < CAPG) { lst[slot] = make_int2(base + 1, __float_as_int(v.y)); slot++; }
                    if (v.z != 0.0f && slot < CAPG) { lst[slot] = make_int2(base + 2, __float_as_int(v.z)); slot++; }
                    if (v.w != 0.0f && slot < CAPG) { lst[slot] = make_int2(base + 3, __float_as_int(v.w)); slot++; }
                }
            }
        }
        for (int jb = nf4 * 4; jb < N; jb++) {           // scalar tail (unused for 12288)
            if (lane == 0) {
                float av = adj[(size_t)i * N + jb];
                if (av != 0.0f) {
                    int slot = atomicAdd(&g_cnt[i], 1);
                    if (slot < CAPG) lst[slot] = make_int2(jb, __float_as_int(av));
                }
            }
        }
        return;
    }

    // ---------------- hqk role ----------------
    for (int idx = threadIdx.x; idx < D * D; idx += blockDim.x) {
        int r = idx >> 6, c = idx & 63;
        sA[r * PD + c] = W [idx];
        sB[r * PD + c] = Wq[idx];
    }
    __syncthreads();

    const int warp   = (blockIdx.x * blockDim.x + threadIdx.x) >> 5;
    const int nwarps = HQKB * 8;

    const float es  = __expf(__ldg(scale));
    const float esq = __expf(__ldg(scale_q));
    const float esk = __expf(__ldg(scale_k));
    const float b0  = __ldg(&b [lane]), b1  = __ldg(&b [lane + 32]);
    const float bq0 = __ldg(&bq[lane]), bq1 = __ldg(&bq[lane + 32]);
    const float bk0 = __ldg(&bk[lane]), bk1 = __ldg(&bk[lane + 32]);

    const int ngroups = (N + 3) >> 2;

    for (int g = warp; g < ngroups; g += nwarps) {
        int r = g * 4;
        float v0[4], v1[4];
#pragma unroll
        for (int k = 0; k < 4; k++) {
            int rr = min(r + k, N - 1);
            v0[k] = x[rr * D + lane];
            v1[k] = x[rr * D + lane + 32];
        }
        float h0[4], h1[4];
        matvec4(sA, v0, v1, b0, b1, lane, h0, h1);
#pragma unroll
        for (int k = 0; k < 4; k++) {
            lorentzify(h0[k], h1[k], es, lane);
            if (r + k < N) {
                g_h[(r + k) * D + lane]      = h0[k];
                g_h[(r + k) * D + lane + 32] = h1[k];
            }
        }
        float q0[4], q1[4];
        matvec4(sB, h0, h1, bq0, bq1, lane, q0, q1);
#pragma unroll
        for (int k = 0; k < 4; k++) {
            lorentzify(q0[k], q1[k], esq, lane);
            if (lane == 0) q0[k] = -q0[k];               // fold Minkowski sign
            if (r + k < N) {
                g_qm[(r + k) * D + lane]      = q0[k];
                g_qm[(r + k) * D + lane + 32] = q1[k];
            }
        }
    }
    __syncthreads();
    for (int idx = threadIdx.x; idx < D * D; idx += blockDim.x) {
        int r = idx >> 6, c = idx & 63;
        sA[r * PD + c] = Wk[idx];
    }
    __syncthreads();
    for (int g = warp; g < ngroups; g += nwarps) {
        int r = g * 4;
        float v0[4], v1[4];
#pragma unroll
        for (int k = 0; k < 4; k++) {
            int rr = min(r + k, N - 1);
            v0[k] = g_h[rr * D + lane];
            v1[k] = g_h[rr * D + lane + 32];
        }
        float k0[4], k1[4];
        matvec4(sA, v0, v1, bk0, bk1, lane, k0, k1);
#pragma unroll
        for (int k = 0; k < 4; k++) {
            lorentzify(k0[k], k1[k], esk, lane);
            if (r + k < N) {
                g_k[(r + k) * D + lane]      = k0[k];
                g_k[(r + k) * D + lane + 32] = k1[k];
            }
        }
    }
}

// Gather: TWO warps per row (each half of the entry list), entries group-local
// (8 lanes per entry: k+h rows as 2xLDG.128 each, dot + 3-stage group reduce,
// group-redundant sigmoid, lane-local dim accumulators). Warp partials combine
// through smem; even warp normalizes and writes. Reg-capped for occupancy.
__global__ void __launch_bounds__(256, 6)
gather_kernel(const float* __restrict__ att_bias,
              const float* __restrict__ att_scale,
              float* __restrict__ out, int N)
{
    __shared__ __align__(16) float s_part[8][64];

    const int lane = threadIdx.x & 31;
    const int w    = threadIdx.x >> 5;          // 0..7
    const int pair = w >> 1;                    // row slot within block (0..3)
    const int half = w & 1;                     // which half of the list
    const int i    = blockIdx.x * 4 + pair;

    const float bias = __ldg(att_bias);
    const float invs = 1.0f / __ldg(att_scale);

    const int grp = lane >> 3;                  // entry within 4-pack
    const int sub = lane & 7;                   // dims [sub*8, sub*8+8)

    float4 acc0 = make_float4(0.f, 0.f, 0.f, 0.f);
    float4 acc1 = make_float4(0.f, 0.f, 0.f, 0.f);

    if (i < N) {
        const float4* qp = (const float4*)&g_qm[(size_t)i * D] + sub * 2;
        const float4 qv0 = __ldg(qp), qv1 = __ldg(qp + 1);

        const int cnt  = min(g_cnt[i], CAPG);
        const int cnt0 = (cnt + 1) >> 1;
        const int lo   = half ? cnt0 : 0;
        const int hi   = half ? cnt  : cnt0;
        const int2* lst = g_list + (size_t)i * CAPG;

        for (int chunk = lo; chunk < hi; chunk += 32) {
            const int mm = min(hi - chunk, 32);
            int2 ent = (lane < mm) ? __ldg(&lst[chunk + lane]) : make_int2(0, 0);
            int   jreg = ent.x;
            float areg = __int_as_float(ent.y);

#pragma unroll 2
            for (int base = 0; base < mm; base += 4) {
                const int  e   = base + grp;
                const int  j   = __shfl_sync(FULL, jreg, e & 31);
                const float av = __shfl_sync(FULL, areg, e & 31);
                const bool act = (e < mm);

                float4 kv0, kv1, hv0, hv1;
                if (act) {
                    const float4* kp = (const float4*)&g_k[(size_t)j * D] + sub * 2;
                    const float4* hp = (const float4*)&g_h[(size_t)j * D] + sub * 2;
                    kv0 = __ldg(kp);  kv1 = __ldg(kp + 1);
                    hv0 = __ldg(hp);  hv1 = __ldg(hp + 1);
                } else {
                    kv0 = kv1 = hv0 = hv1 = make_float4(0.f, 0.f, 0.f, 0.f);
                }

                float d0 = qv0.x * kv0.x + qv0.y * kv0.y;
                float d1 = qv0.z * kv0.z + qv0.w * kv0.w;
                d0 = fmaf(qv1.x, kv1.x, d0); d1 = fmaf(qv1.y, kv1.y, d1);
                d0 = fmaf(qv1.z, kv1.z, d0); d1 = fmaf(qv1.w, kv1.w, d1);
                float d = d0 + d1;
                d += __shfl_xor_sync(FULL, d, 4);
                d += __shfl_xor_sync(FULL, d, 2);
                d += __shfl_xor_sync(FULL, d, 1);

                float att = act ? av / (1.0f + __expf(-fmaf(2.0f + 2.0f * d, invs, bias))) : 0.0f;

                acc0.x = fmaf(att, hv0.x, acc0.x); acc0.y = fmaf(att, hv0.y, acc0.y);
                acc0.z = fmaf(att, hv0.z, acc0.z); acc0.w = fmaf(att, hv0.w, acc0.w);
                acc1.x = fmaf(att, hv1.x, acc1.x); acc1.y = fmaf(att, hv1.y, acc1.y);
                acc1.z = fmaf(att, hv1.z, acc1.z); acc1.w = fmaf(att, hv1.w, acc1.w);
            }
        }
    }

    // warp-local combine across the 4 groups (lanes with equal sub share dims)
#pragma unroll
    for (int off = 8; off <= 16; off <<= 1) {
        acc0.x += __shfl_xor_sync(FULL, acc0.x, off);
        acc0.y += __shfl_xor_sync(FULL, acc0.y, off);
        acc0.z += __shfl_xor_sync(FULL, acc0.z, off);
        acc0.w += __shfl_xor_sync(FULL, acc0.w, off);
        acc1.x += __shfl_xor_sync(FULL, acc1.x, off);
        acc1.y += __shfl_xor_sync(FULL, acc1.y, off);
        acc1.z += __shfl_xor_sync(FULL, acc1.z, off);
        acc1.w += __shfl_xor_sync(FULL, acc1.w, off);
    }
    if (lane < 8) {
        *(float4*)&s_part[w][sub * 8]     = acc0;
        *(float4*)&s_part[w][sub * 8 + 4] = acc1;
    }
    __syncthreads();

    if (half == 0 && i < N && lane < 8) {
        float4 p0 = *(const float4*)&s_part[w + 1][sub * 8];
        float4 p1 = *(const float4*)&s_part[w + 1][sub * 8 + 4];
        float4 c0 = make_float4(acc0.x + p0.x, acc0.y + p0.y, acc0.z + p0.z, acc0.w + p0.w);
        float4 c1 = make_float4(acc1.x + p1.x, acc1.y + p1.y, acc1.z + p1.z, acc1.w + p1.w);

        // Lorentz row normalization: inner = -s0^2 + sum_{d>=1} s_d^2
        float ssq = c0.x * c0.x + c0.y * c0.y + c0.z * c0.z + c0.w * c0.w
                  + c1.x * c1.x + c1.y * c1.y + c1.z * c1.z + c1.w * c1.w;
#pragma unroll
        for (int off = 1; off <= 4; off <<= 1) ssq += __shfl_xor_sync(0xFFu, ssq, off);
        float s0    = __shfl_sync(0xFFu, c0.x, 0);       // dim 0 lives in lane 0
        float inner = ssq - 2.0f * s0 * s0;
        float invdn = rsqrtf(fmaxf(fabsf(inner), 1e-8f));

        float4* op = (float4*)&out[(size_t)i * D] + sub * 2;
        op[0] = make_float4(c0.x * invdn, c0.y * invdn, c0.z * invdn, c0.w * invdn);
        op[1] = make_float4(c1.x * invdn, c1.y * invdn, c1.z * invdn, c1.w * invdn);
    }
}

extern "C" void kernel_launch(void* const* d_in, const int* in_sizes, int n_in,
                              void* d_out, int out_size)
{
    const float* x         = (const float*)d_in[0];
    const float* adj       = (const float*)d_in[1];
    const float* W         = (const float*)d_in[2];
    const float* b         = (const float*)d_in[3];
    const float* scale     = (const float*)d_in[4];
    const float* Wq        = (const float*)d_in[5];
    const float* bq        = (const float*)d_in[6];
    const float* scale_q   = (const float*)d_in[7];
    const float* Wk        = (const float*)d_in[8];
    const float* bk        = (const float*)d_in[9];
    const float* scale_k   = (const float*)d_in[10];
    const float* att_bias  = (const float*)d_in[11];
    const float* att_scale = (const float*)d_in[12];

    const int N = in_sizes[0] / D;                 // 12288
    const int scan_blocks = (N + 7) / 8;           // one warp per adj row

    fused1_kernel<<<HQKB + scan_blocks, 256>>>(x, W, b, scale, Wq, bq, scale_q,
                                               Wk, bk, scale_k, adj, N);
    gather_kernel<<<(N + 3) / 4, 256>>>(att_bias, att_scale, (float*)d_out, N);
}

// round 14
// speedup vs baseline: 1.0554x; 1.0554x over previous
#include <cuda_runtime.h>

#define D     64
#define PD    68            // padded smem row stride: 16B-aligned rows, conflict-free LDS.128
#define NMAX  12288
#define FULL  0xffffffffu
#define CAPG  128           // per-row nonzero list capacity (mean ~25, 20+ sigma headroom)
#define HQKB  148           // blocks doing hqk (one per SM in wave 1)

// Scratch (allocation-free contract: __device__ globals)
__device__ float g_h [NMAX * D];
__device__ float g_qm[NMAX * D];            // q with first component pre-negated
__device__ float g_k [NMAX * D];
__device__ int   g_cnt [NMAX];
__device__ int2  g_list[(size_t)NMAX * CAPG];   // {col j, float bits of adj value}

// 4-rows-per-warp cooperative 64x64 matvec; weights as float4 from padded smem.
__device__ __forceinline__ void matvec4(const float* __restrict__ sW,
                                        const float v0[4], const float v1[4],
                                        float bb0, float bb1, int lane,
                                        float o0[4], float o1[4])
{
    const float4* r0 = (const float4*)(sW + lane * PD);
    const float4* r1 = (const float4*)(sW + (lane + 32) * PD);
    float a0[4], a1[4];
#pragma unroll
    for (int k = 0; k < 4; k++) { a0[k] = bb0; a1[k] = bb1; }
#pragma unroll
    for (int c4 = 0; c4 < 8; c4++) {
        float4 w0 = r0[c4], w1 = r1[c4];
#pragma unroll
        for (int k = 0; k < 4; k++) {
            float x0 = __shfl_sync(FULL, v0[k], 4 * c4 + 0);
            float x1 = __shfl_sync(FULL, v0[k], 4 * c4 + 1);
            float x2 = __shfl_sync(FULL, v0[k], 4 * c4 + 2);
            float x3 = __shfl_sync(FULL, v0[k], 4 * c4 + 3);
            a0[k] = fmaf(x0, w0.x, a0[k]); a1[k] = fmaf(x0, w1.x, a1[k]);
            a0[k] = fmaf(x1, w0.y, a0[k]); a1[k] = fmaf(x1, w1.y, a1[k]);
            a0[k] = fmaf(x2, w0.z, a0[k]); a1[k] = fmaf(x2, w1.z, a1[k]);
            a0[k] = fmaf(x3, w0.w, a0[k]); a1[k] = fmaf(x3, w1.w, a1[k]);
        }
    }
#pragma unroll
    for (int c4 = 8; c4 < 16; c4++) {
        float4 w0 = r0[c4], w1 = r1[c4];
#pragma unroll
        for (int k = 0; k < 4; k++) {
            float x0 = __shfl_sync(FULL, v1[k], 4 * (c4 - 8) + 0);
            float x1 = __shfl_sync(FULL, v1[k], 4 * (c4 - 8) + 1);
            float x2 = __shfl_sync(FULL, v1[k], 4 * (c4 - 8) + 2);
            float x3 = __shfl_sync(FULL, v1[k], 4 * (c4 - 8) + 3);
            a0[k] = fmaf(x0, w0.x, a0[k]); a1[k] = fmaf(x0, w1.x, a1[k]);
            a0[k] = fmaf(x1, w0.y, a0[k]); a1[k] = fmaf(x1, w1.y, a1[k]);
            a0[k] = fmaf(x2, w0.z, a0[k]); a1[k] = fmaf(x2, w1.z, a1[k]);
            a0[k] = fmaf(x3, w0.w, a0[k]); a1[k] = fmaf(x3, w1.w, a1[k]);
        }
    }
#pragma unroll
    for (int k = 0; k < 4; k++) { o0[k] = a0[k]; o1[k] = a1[k]; }
}

__device__ __forceinline__ void lorentzify(float& h0, float& h1, float escale, int lane)
{
    float t    = __shfl_sync(FULL, h0, 0);
    float time = escale / (1.0f + __expf(-t)) + 1.1f;
    float sq   = ((lane == 0) ? 0.0f : h0 * h0) + h1 * h1;
#pragma unroll
    for (int o = 16; o > 0; o >>= 1) sq += __shfl_xor_sync(FULL, sq, o);
    sq = fmaxf(sq, 1e-8f);
    float ss = sqrtf((time * time - 1.0f) / sq);
    h0 = (lane == 0) ? time : h0 * ss;
    h1 *= ss;
}

// Blocks [0,HQKB): compute h/qm/k (hidden under the adj stream).
// Blocks [HQKB,..): one warp per adj row — stream adj, append nonzeros to
// per-row global lists.
__global__ void __launch_bounds__(256)
fused1_kernel(const float* __restrict__ x,
              const float* __restrict__ W,  const float* __restrict__ b,  const float* __restrict__ scale,
              const float* __restrict__ Wq, const float* __restrict__ bq, const float* __restrict__ scale_q,
              const float* __restrict__ Wk, const float* __restrict__ bk, const float* __restrict__ scale_k,
              const float* __restrict__ adj, int N)
{
    __shared__ __align__(16) float sA[D * PD];
    __shared__ __align__(16) float sB[D * PD];

    const int lane = threadIdx.x & 31;

    if (blockIdx.x >= HQKB) {
        // ---------------- scan role: one warp per adj row ----------------
        const int i = (blockIdx.x - HQKB) * 8 + (threadIdx.x >> 5);
        if (i >= N) return;
        if (lane == 0) g_cnt[i] = 0;
        __syncwarp();

        const float4* arow = (const float4*)(adj + (size_t)i * N);
        const int nf4 = N >> 2;
        int2* lst = g_list + (size_t)i * CAPG;

        for (int it = 0; it < nf4; it += 256) {          // 1024 cols/iter, MLP=8
            float4 a[8];
#pragma unroll
            for (int u = 0; u < 8; u++) {
                int idx = it + u * 32 + lane;
                a[u] = (idx < nf4) ? __ldcs(&arow[idx]) : make_float4(0.f, 0.f, 0.f, 0.f);
            }
#pragma unroll
            for (int u = 0; u < 8; u++) {
                float4 v = a[u];
                if ((v.x != 0.0f) | (v.y != 0.0f) | (v.z != 0.0f) | (v.w != 0.0f)) {
                    int base = (it + u * 32 + lane) * 4;
                    int n = (v.x != 0.0f) + (v.y != 0.0f) + (v.z != 0.0f) + (v.w != 0.0f);
                    int slot = atomicAdd(&g_cnt[i], n);
                    if (v.x != 0.0f && slot < CAPG) { lst[slot] = make_int2(base,     __float_as_int(v.x)); slot++; }
                    if (v.y != 0.0f && slot < CAPG) { lst[slot] = make_int2(base + 1, __float_as_int(v.y)); slot++; }
                    if (v.z != 0.0f && slot < CAPG) { lst[slot] = make_int2(base + 2, __float_as_int(v.z)); slot++; }
                    if (v.w != 0.0f && slot < CAPG) { lst[slot] = make_int2(base + 3, __float_as_int(v.w)); slot++; }
                }
            }
        }
        for (int jb = nf4 * 4; jb < N; jb++) {           // scalar tail (unused for 12288)
            if (lane == 0) {
                float av = adj[(size_t)i * N + jb];
                if (av != 0.0f) {
                    int slot = atomicAdd(&g_cnt[i], 1);
                    if (slot < CAPG) lst[slot] = make_int2(jb, __float_as_int(av));
                }
            }
        }
        return;
    }

    // ---------------- hqk role ----------------
    for (int idx = threadIdx.x; idx < D * D; idx += blockDim.x) {
        int r = idx >> 6, c = idx & 63;
        sA[r * PD + c] = W [idx];
        sB[r * PD + c] = Wq[idx];
    }
    __syncthreads();

    const int warp   = (blockIdx.x * blockDim.x + threadIdx.x) >> 5;
    const int nwarps = HQKB * 8;

    const float es  = __expf(__ldg(scale));
    const float esq = __expf(__ldg(scale_q));
    const float esk = __expf(__ldg(scale_k));
    const float b0  = __ldg(&b [lane]), b1  = __ldg(&b [lane + 32]);
    const float bq0 = __ldg(&bq[lane]), bq1 = __ldg(&bq[lane + 32]);
    const float bk0 = __ldg(&bk[lane]), bk1 = __ldg(&bk[lane + 32]);

    const int ngroups = (N + 3) >> 2;

    for (int g = warp; g < ngroups; g += nwarps) {
        int r = g * 4;
        float v0[4], v1[4];
#pragma unroll
        for (int k = 0; k < 4; k++) {
            int rr = min(r + k, N - 1);
            v0[k] = x[rr * D + lane];
            v1[k] = x[rr * D + lane + 32];
        }
        float h0[4], h1[4];
        matvec4(sA, v0, v1, b0, b1, lane, h0, h1);
#pragma unroll
        for (int k = 0; k < 4; k++) {
            lorentzify(h0[k], h1[k], es, lane);
            if (r + k < N) {
                g_h[(r + k) * D + lane]      = h0[k];
                g_h[(r + k) * D + lane + 32] = h1[k];
            }
        }
        float q0[4], q1[4];
        matvec4(sB, h0, h1, bq0, bq1, lane, q0, q1);
#pragma unroll
        for (int k = 0; k < 4; k++) {
            lorentzify(q0[k], q1[k], esq, lane);
            if (lane == 0) q0[k] = -q0[k];               // fold Minkowski sign
            if (r + k < N) {
                g_qm[(r + k) * D + lane]      = q0[k];
                g_qm[(r + k) * D + lane + 32] = q1[k];
            }
        }
    }
    __syncthreads();
    for (int idx = threadIdx.x; idx < D * D; idx += blockDim.x) {
        int r = idx >> 6, c = idx & 63;
        sA[r * PD + c] = Wk[idx];
    }
    __syncthreads();
    for (int g = warp; g < ngroups; g += nwarps) {
        int r = g * 4;
        float v0[4], v1[4];
#pragma unroll
        for (int k = 0; k < 4; k++) {
            int rr = min(r + k, N - 1);
            v0[k] = g_h[rr * D + lane];
            v1[k] = g_h[rr * D + lane + 32];
        }
        float k0[4], k1[4];
        matvec4(sA, v0, v1, bk0, bk1, lane, k0, k1);
#pragma unroll
        for (int k = 0; k < 4; k++) {
            lorentzify(k0[k], k1[k], esk, lane);
            if (r + k < N) {
                g_k[(r + k) * D + lane]      = k0[k];
                g_k[(r + k) * D + lane + 32] = k1[k];
            }
        }
    }
}

// Gather (R12 structure): one warp per row, entries fully group-local
// (8 lanes per entry). List loaded once per 32 entries into registers; per
// pack each group does k-row + h-row 2xLDG.128 each (unrolled across packs
// for MLP), dot + 3-stage group reduce, group-redundant sigmoid, lane-local
// dim accumulators. Cross-group combine + Lorentz norm once per row.
// launch_bounds(256,5): cap regs at 51 -> 5 blocks/SM (40 warps vs 32).
__global__ void __launch_bounds__(256, 5)
gather_kernel(const float* __restrict__ att_bias,
              const float* __restrict__ att_scale,
              float* __restrict__ out, int N)
{
    const int lane = threadIdx.x & 31;
    const int i    = (blockIdx.x * blockDim.x + threadIdx.x) >> 5;
    if (i >= N) return;

    const float bias = __ldg(att_bias);
    const float invs = 1.0f / __ldg(att_scale);

    const int grp = lane >> 3;      // which entry in the 4-pack
    const int sub = lane & 7;       // dims [sub*8, sub*8+8)

    // qm_i dims for this lane's slice (replicated across the 4 groups)
    const float4* qp = (const float4*)&g_qm[(size_t)i * D] + sub * 2;
    const float4 qv0 = __ldg(qp), qv1 = __ldg(qp + 1);

    const int2* lst = g_list + (size_t)i * CAPG;
    const int cnt = min(g_cnt[i], CAPG);

    float4 acc0 = make_float4(0.f, 0.f, 0.f, 0.f);
    float4 acc1 = make_float4(0.f, 0.f, 0.f, 0.f);

    for (int chunk = 0; chunk < cnt; chunk += 32) {
        const int mm = min(cnt - chunk, 32);
        int2 ent = (lane < mm) ? __ldg(&lst[chunk + lane]) : make_int2(0, 0);
        int   jreg = ent.x;
        float areg = __int_as_float(ent.y);

#pragma unroll 4
        for (int base = 0; base < mm; base += 4) {
            const int  e   = base + grp;
            const int  j   = __shfl_sync(FULL, jreg, e & 31);
            const float av = __shfl_sync(FULL, areg, e & 31);
            const bool act = (e < mm);

            float4 kv0, kv1, hv0, hv1;
            if (act) {
                const float4* kp = (const float4*)&g_k[(size_t)j * D] + sub * 2;
                const float4* hp = (const float4*)&g_h[(size_t)j * D] + sub * 2;
                kv0 = __ldg(kp);  kv1 = __ldg(kp + 1);
                hv0 = __ldg(hp);  hv1 = __ldg(hp + 1);
            } else {
                kv0 = kv1 = hv0 = hv1 = make_float4(0.f, 0.f, 0.f, 0.f);
            }

            float d0 = qv0.x * kv0.x + qv0.y * kv0.y;
            float d1 = qv0.z * kv0.z + qv0.w * kv0.w;
            d0 = fmaf(qv1.x, kv1.x, d0); d1 = fmaf(qv1.y, kv1.y, d1);
            d0 = fmaf(qv1.z, kv1.z, d0); d1 = fmaf(qv1.w, kv1.w, d1);
            float d = d0 + d1;
            d += __shfl_xor_sync(FULL, d, 4);
            d += __shfl_xor_sync(FULL, d, 2);
            d += __shfl_xor_sync(FULL, d, 1);

            float att = act ? av / (1.0f + __expf(-fmaf(2.0f + 2.0f * d, invs, bias))) : 0.0f;

            acc0.x = fmaf(att, hv0.x, acc0.x); acc0.y = fmaf(att, hv0.y, acc0.y);
            acc0.z = fmaf(att, hv0.z, acc0.z); acc0.w = fmaf(att, hv0.w, acc0.w);
            acc1.x = fmaf(att, hv1.x, acc1.x); acc1.y = fmaf(att, hv1.y, acc1.y);
            acc1.z = fmaf(att, hv1.z, acc1.z); acc1.w = fmaf(att, hv1.w, acc1.w);
        }
    }

    // combine partial sums across the 4 groups (lanes with equal sub share dims)
#pragma unroll
    for (int off = 8; off <= 16; off <<= 1) {
        acc0.x += __shfl_xor_sync(FULL, acc0.x, off);
        acc0.y += __shfl_xor_sync(FULL, acc0.y, off);
        acc0.z += __shfl_xor_sync(FULL, acc0.z, off);
        acc0.w += __shfl_xor_sync(FULL, acc0.w, off);
        acc1.x += __shfl_xor_sync(FULL, acc1.x, off);
        acc1.y += __shfl_xor_sync(FULL, acc1.y, off);
        acc1.z += __shfl_xor_sync(FULL, acc1.z, off);
        acc1.w += __shfl_xor_sync(FULL, acc1.w, off);
    }

    // Lorentz row normalization: inner = -s0^2 + sum_{d>=1} s_d^2
    float ssq = acc0.x * acc0.x + acc0.y * acc0.y + acc0.z * acc0.z + acc0.w * acc0.w
              + acc1.x * acc1.x + acc1.y * acc1.y + acc1.z * acc1.z + acc1.w * acc1.w;
#pragma unroll
    for (int off = 1; off <= 4; off <<= 1) ssq += __shfl_xor_sync(FULL, ssq, off);
    float s0    = __shfl_sync(FULL, acc0.x, 0);          // dim 0 (lane 0 = grp0,sub0)
    float inner = ssq - 2.0f * s0 * s0;
    float invdn = rsqrtf(fmaxf(fabsf(inner), 1e-8f));

    if (lane < 8) {                                      // group 0 writes the row
        float4 o0 = make_float4(acc0.x * invdn, acc0.y * invdn, acc0.z * invdn, acc0.w * invdn);
        float4 o1 = make_float4(acc1.x * invdn, acc1.y * invdn, acc1.z * invdn, acc1.w * invdn);
        float4* op = (float4*)&out[(size_t)i * D] + sub * 2;
        op[0] = o0;
        op[1] = o1;
    }
}

extern "C" void kernel_launch(void* const* d_in, const int* in_sizes, int n_in,
                              void* d_out, int out_size)
{
    const float* x         = (const float*)d_in[0];
    const float* adj       = (const float*)d_in[1];
    const float* W         = (const float*)d_in[2];
    const float* b         = (const float*)d_in[3];
    const float* scale     = (const float*)d_in[4];
    const float* Wq        = (const float*)d_in[5];
    const float* bq        = (const float*)d_in[6];
    const float* scale_q   = (const float*)d_in[7];
    const float* Wk        = (const float*)d_in[8];
    const float* bk        = (const float*)d_in[9];
    const float* scale_k   = (const float*)d_in[10];
    const float* att_bias  = (const float*)d_in[11];
    const float* att_scale = (const float*)d_in[12];

    const int N = in_sizes[0] / D;                 // 12288
    const int scan_blocks = (N + 7) / 8;           // one warp per adj row

    fused1_kernel<<<HQKB + scan_blocks, 256>>>(x, W, b, scale, Wq, bq, scale_q,
                                               Wk, bk, scale_k, adj, N);
    gather_kernel<<<(N + 7) / 8, 256>>>(att_bias, att_scale, (float*)d_out, N);
}